// round 4
// baseline (speedup 1.0000x reference)
#include <cuda_runtime.h>
#include <cuda_bf16.h>
#include <math.h>
#include <stdint.h>

#define TT 2048
#define BB 64
#define II 128
#define HH 128
#define FCN 32

#define TC 128                  // timesteps per CTA tile (= GEMM M)
#define NCHUNK (TT / TC)        // 16
#define NCTA (NCHUNK * BB)      // 1024

// ---------------- global scratch ----------------
// pre-converted W bf16 hi/lo swizzled smem-images: [gate][b][hi 32K | lo 32K]
__device__ __align__(128) unsigned char g_Wimg[3][BB][65536];
// per-tile activations: p = sigmoid(i)*tanh(g), f = sigmoid(f)
__device__ float g_P [NCTA * TC * HH];
__device__ float g_Fg[NCTA * TC * HH];
// chunk-scan outputs
__device__ float g_F[BB * NCHUNK * HH];
__device__ float g_C[BB * NCHUNK * HH];

// ---------------- smem layout (bytes) ----------------
// Xhi [0,32K) | Xlo [32K,64K) | W0 [64K,128K) | W1 [128K,192K)
#define SX_HI 0
#define SX_LO 32768
#define SW0   65536
#define SW1   131072
#define SMEM_BYTES 196608

// ---------------- helpers ----------------
__device__ __forceinline__ uint32_t smem_u32(const void* p) {
    uint32_t a;
    asm("{ .reg .u64 t; cvta.to.shared.u64 t, %1; cvt.u32.u64 %0, t; }" : "=r"(a) : "l"(p));
    return a;
}
__device__ __forceinline__ float sigmoidf_(float x) { return 1.0f / (1.0f + expf(-x)); }

__device__ __forceinline__ void cp_async16(uint32_t saddr, const void* gaddr) {
    asm volatile("cp.async.cg.shared.global [%0], [%1], 16;" :: "r"(saddr), "l"(gaddr) : "memory");
}
#define CP_COMMIT() asm volatile("cp.async.commit_group;" ::: "memory")
#define CP_WAIT(n)  asm volatile("cp.async.wait_group %0;" :: "n"(n) : "memory")

#define LDSM_X4(r0, r1, r2, r3, addr) \
    asm volatile("ldmatrix.sync.aligned.m8n8.x4.shared.b16 {%0,%1,%2,%3}, [%4];" \
                 : "=r"(r0), "=r"(r1), "=r"(r2), "=r"(r3) : "r"(addr))

#define MMA16816(d, a, b) \
    asm volatile("mma.sync.aligned.m16n8k16.row.col.f32.bf16.bf16.f32 " \
                 "{%0,%1,%2,%3},{%4,%5,%6,%7},{%8,%9},{%0,%1,%2,%3};" \
                 : "+f"((d)[0]), "+f"((d)[1]), "+f"((d)[2]), "+f"((d)[3]) \
                 : "r"((a)[0]), "r"((a)[1]), "r"((a)[2]), "r"((a)[3]), \
                   "r"((b)[0]), "r"((b)[1]))

// convert fp32 [128 x 128] tile (row stride rs floats) -> bf16 hi/lo swizzled
// images (256B rows; 16B chunk c16 stored at c16 ^ (row & 7)).
__device__ __forceinline__ void conv_img(const float* __restrict__ src, int rs,
                                         unsigned char* __restrict__ hi,
                                         unsigned char* __restrict__ lo, int tid) {
    #pragma unroll
    for (int it = 0; it < 8; ++it) {
        const int idx = tid + it * 256;
        const int r = idx >> 4, c16 = idx & 15;
        const float4* g4 = (const float4*)(src + (size_t)r * rs + c16 * 8);
        const float4 v0 = g4[0], v1 = g4[1];
        const float f[8] = {v0.x, v0.y, v0.z, v0.w, v1.x, v1.y, v1.z, v1.w};
        uint32_t h4[4], l4[4];
        #pragma unroll
        for (int k = 0; k < 4; ++k) {
            __nv_bfloat16 h0 = __float2bfloat16_rn(f[2 * k]);
            __nv_bfloat16 h1 = __float2bfloat16_rn(f[2 * k + 1]);
            __nv_bfloat16 l0 = __float2bfloat16_rn(f[2 * k]     - __bfloat162float(h0));
            __nv_bfloat16 l1 = __float2bfloat16_rn(f[2 * k + 1] - __bfloat162float(h1));
            h4[k] = (uint32_t)__bfloat16_as_ushort(h0) | ((uint32_t)__bfloat16_as_ushort(h1) << 16);
            l4[k] = (uint32_t)__bfloat16_as_ushort(l0) | ((uint32_t)__bfloat16_as_ushort(l1) << 16);
        }
        const uint32_t off = (uint32_t)r * 256u + (uint32_t)(((c16 ^ (r & 7))) * 16);
        *(uint4*)(hi + off) = make_uint4(h4[0], h4[1], h4[2], h4[3]);
        *(uint4*)(lo + off) = make_uint4(l4[0], l4[1], l4[2], l4[3]);
    }
}

// one gate GEMM: acc += Xhi*Whi + Xhi*Wlo + Xlo*Whi   (W image: hi at w, lo at w+32K)
__device__ __forceinline__ void gate_mma(uint32_t xhi, uint32_t xlo, uint32_t w,
                                         float (&acc)[4][4][4], int lane,
                                         int m_base, int n_base) {
    const int arow = (lane & 7) + ((lane >> 3) & 1) * 8;  // + m_base + mt*16
    const int ak   = (lane >> 4) & 1;                     // A k-chunk select
    const int brow = (lane & 7) + ((lane >> 4) & 1) * 8;  // + n_base + nh*16
    const int bk   = (lane >> 3) & 1;                     // B k-chunk select
    #pragma unroll
    for (int k = 0; k < 8; ++k) {
        uint32_t a[4][4], bh[2][4], bl[2][4];
        #pragma unroll
        for (int mt = 0; mt < 4; ++mt) {
            const int r = m_base + mt * 16 + arow;
            const uint32_t ad = xhi + (uint32_t)r * 256u
                              + (uint32_t)((((2 * k + ak) ^ (r & 7))) * 16);
            LDSM_X4(a[mt][0], a[mt][1], a[mt][2], a[mt][3], ad);
        }
        #pragma unroll
        for (int nh = 0; nh < 2; ++nh) {
            const int n = n_base + nh * 16 + brow;
            const uint32_t c = (uint32_t)((((2 * k + bk) ^ (n & 7))) * 16)
                             + (uint32_t)n * 256u;
            LDSM_X4(bh[nh][0], bh[nh][1], bh[nh][2], bh[nh][3], w + c);
            LDSM_X4(bl[nh][0], bl[nh][1], bl[nh][2], bl[nh][3], w + 32768u + c);
        }
        #pragma unroll
        for (int mt = 0; mt < 4; ++mt)
            #pragma unroll
            for (int nt = 0; nt < 4; ++nt) {
                MMA16816(acc[mt][nt], a[mt], &bh[nt >> 1][(nt & 1) * 2]);
                MMA16816(acc[mt][nt], a[mt], &bl[nt >> 1][(nt & 1) * 2]);
            }
        #pragma unroll
        for (int mt = 0; mt < 4; ++mt) {
            const int r = m_base + mt * 16 + arow;
            const uint32_t ad = xlo + (uint32_t)r * 256u
                              + (uint32_t)((((2 * k + ak) ^ (r & 7))) * 16);
            LDSM_X4(a[mt][0], a[mt][1], a[mt][2], a[mt][3], ad);
        }
        #pragma unroll
        for (int mt = 0; mt < 4; ++mt)
            #pragma unroll
            for (int nt = 0; nt < 4; ++nt)
                MMA16816(acc[mt][nt], a[mt], &bh[nt >> 1][(nt & 1) * 2]);
    }
}

// ---------------------------------------------------------------------------
// K0: pre-convert W (g,i,f) per batch into bf16 hi/lo swizzled images
// ---------------------------------------------------------------------------
__global__ __launch_bounds__(256)
void alstm_wconv(const float* __restrict__ wg, const float* __restrict__ wi,
                 const float* __restrict__ wf) {
    const int gate = blockIdx.x >> 6;
    const int b    = blockIdx.x & 63;
    const float* src = ((gate == 0) ? wg : (gate == 1) ? wi : wf) + (size_t)b * HH * II;
    conv_img(src, II, g_Wimg[gate][b], g_Wimg[gate][b] + 32768, threadIdx.x);
}

// ---------------------------------------------------------------------------
// K1: per (chunk, batch): bf16-split tensor-core gate GEMMs + act + chunk scan
// ---------------------------------------------------------------------------
__global__ __launch_bounds__(256, 1)
void alstm_main(const float* __restrict__ x,
                const float* __restrict__ bg, const float* __restrict__ bi,
                const float* __restrict__ bf) {
    extern __shared__ unsigned char smem[];
    const int chunk = blockIdx.x, b = blockIdx.y;
    const int tid = threadIdx.x, lane = tid & 31, warp = tid >> 5;
    const int m_base = (warp >> 2) * 64;     // 2 warps over M
    const int n_base = (warp & 3) * 32;      // 4 warps over N
    const uint32_t sb = smem_u32(smem);
    const size_t pbase = (size_t)(b * NCHUNK + chunk) * TC * HH;

    // stage W_g -> W0 (async, overlaps X conversion)
    {
        const unsigned char* src = g_Wimg[0][b];
        #pragma unroll
        for (int i = 0; i < 16; ++i)
            cp_async16(sb + SW0 + tid * 16 + i * 4096, src + tid * 16 + i * 4096);
        CP_COMMIT();
    }
    // convert X chunk [TC x II] -> Xhi/Xlo images
    conv_img(x + ((size_t)(chunk * TC) * BB + b) * II, BB * II,
             smem + SX_HI, smem + SX_LO, tid);
    // stage W_i -> W1
    {
        const unsigned char* src = g_Wimg[1][b];
        #pragma unroll
        for (int i = 0; i < 16; ++i)
            cp_async16(sb + SW1 + tid * 16 + i * 4096, src + tid * 16 + i * 4096);
        CP_COMMIT();
    }
    CP_WAIT(1);          // W_g landed
    __syncthreads();

    float acc[4][4][4], vg[4][4][4];

    // ---- gate g ----
    #pragma unroll
    for (int mt = 0; mt < 4; ++mt)
        #pragma unroll
        for (int nt = 0; nt < 4; ++nt)
            #pragma unroll
            for (int e = 0; e < 4; ++e) acc[mt][nt][e] = 0.0f;
    gate_mma(sb + SX_HI, sb + SX_LO, sb + SW0, acc, lane, m_base, n_base);
    #pragma unroll
    for (int nt = 0; nt < 4; ++nt) {
        const int h0 = n_base + nt * 8 + 2 * (lane & 3);
        const float2 bv = *(const float2*)(bg + b * HH + h0);
        #pragma unroll
        for (int mt = 0; mt < 4; ++mt) {
            vg[mt][nt][0] = tanhf(acc[mt][nt][0] + bv.x);
            vg[mt][nt][1] = tanhf(acc[mt][nt][1] + bv.y);
            vg[mt][nt][2] = tanhf(acc[mt][nt][2] + bv.x);
            vg[mt][nt][3] = tanhf(acc[mt][nt][3] + bv.y);
        }
    }
    __syncthreads();     // everyone done reading W0
    // stage W_f -> W0
    {
        const unsigned char* src = g_Wimg[2][b];
        #pragma unroll
        for (int i = 0; i < 16; ++i)
            cp_async16(sb + SW0 + tid * 16 + i * 4096, src + tid * 16 + i * 4096);
        CP_COMMIT();
    }
    CP_WAIT(1);          // W_i landed
    __syncthreads();

    // ---- gate i ----  (p = sigmoid(i) * tanh(g))
    #pragma unroll
    for (int mt = 0; mt < 4; ++mt)
        #pragma unroll
        for (int nt = 0; nt < 4; ++nt)
            #pragma unroll
            for (int e = 0; e < 4; ++e) acc[mt][nt][e] = 0.0f;
    gate_mma(sb + SX_HI, sb + SX_LO, sb + SW1, acc, lane, m_base, n_base);
    #pragma unroll
    for (int nt = 0; nt < 4; ++nt) {
        const int h0 = n_base + nt * 8 + 2 * (lane & 3);
        const float2 bv = *(const float2*)(bi + b * HH + h0);
        #pragma unroll
        for (int mt = 0; mt < 4; ++mt) {
            const int t0 = m_base + mt * 16 + (lane >> 2), t1 = t0 + 8;
            const float p0 = sigmoidf_(acc[mt][nt][0] + bv.x) * vg[mt][nt][0];
            const float p1 = sigmoidf_(acc[mt][nt][1] + bv.y) * vg[mt][nt][1];
            const float p2 = sigmoidf_(acc[mt][nt][2] + bv.x) * vg[mt][nt][2];
            const float p3 = sigmoidf_(acc[mt][nt][3] + bv.y) * vg[mt][nt][3];
            *(float2*)(g_P + pbase + (size_t)t0 * HH + h0) = make_float2(p0, p1);
            *(float2*)(g_P + pbase + (size_t)t1 * HH + h0) = make_float2(p2, p3);
        }
    }
    CP_WAIT(0);          // W_f landed
    __syncthreads();

    // ---- gate f ----
    #pragma unroll
    for (int mt = 0; mt < 4; ++mt)
        #pragma unroll
        for (int nt = 0; nt < 4; ++nt)
            #pragma unroll
            for (int e = 0; e < 4; ++e) acc[mt][nt][e] = 0.0f;
    gate_mma(sb + SX_HI, sb + SX_LO, sb + SW0, acc, lane, m_base, n_base);
    #pragma unroll
    for (int nt = 0; nt < 4; ++nt) {
        const int h0 = n_base + nt * 8 + 2 * (lane & 3);
        const float2 bv = *(const float2*)(bf + b * HH + h0);
        #pragma unroll
        for (int mt = 0; mt < 4; ++mt) {
            const int t0 = m_base + mt * 16 + (lane >> 2), t1 = t0 + 8;
            const float f0 = sigmoidf_(acc[mt][nt][0] + bv.x);
            const float f1 = sigmoidf_(acc[mt][nt][1] + bv.y);
            const float f2 = sigmoidf_(acc[mt][nt][2] + bv.x);
            const float f3 = sigmoidf_(acc[mt][nt][3] + bv.y);
            *(float2*)(g_Fg + pbase + (size_t)t0 * HH + h0) = make_float2(f0, f1);
            *(float2*)(g_Fg + pbase + (size_t)t1 * HH + h0) = make_float2(f2, f3);
        }
    }
    __syncthreads();     // block-scope visibility of g_P / g_Fg

    // ---- chunk-local scan: c_t = f*c + p ; F = prod f ----
    if (tid < HH) {
        const float* P  = g_P  + pbase + tid;
        const float* Fv = g_Fg + pbase + tid;
        float c = 0.0f, F = 1.0f;
        #pragma unroll 8
        for (int t = 0; t < TC; ++t) {
            const float fv = Fv[(size_t)t * HH];
            c = fmaf(fv, c, P[(size_t)t * HH]);
            F *= fv;
        }
        const int idx = (b * NCHUNK + chunk) * HH + tid;
        g_F[idx] = F;
        g_C[idx] = c;
    }
}

// ---------------------------------------------------------------------------
// K2: per batch: o-gate at t=T-1, chunk combine, classifier, log_softmax
// ---------------------------------------------------------------------------
__global__ __launch_bounds__(128)
void alstm_finish(const float* __restrict__ x,
                  const float* __restrict__ w_o,
                  const float* __restrict__ b_o,
                  const float* __restrict__ fc1_w,
                  const float* __restrict__ fc1_b,
                  const float* __restrict__ fc2_w,
                  const float* __restrict__ fc2_b,
                  float* __restrict__ out) {
    const int b = blockIdx.x, tid = threadIdx.x;
    __shared__ __align__(16) float sxl[II];
    __shared__ float s_opre[HH], s_hf[HH], s_z1[FCN];

    sxl[tid] = x[((size_t)(TT - 1) * BB + b) * II + tid];
    __syncthreads();

    {   // o preactivation: warp-cooperative dots
        const int wid = tid >> 5, lane = tid & 31;
        const float4 xv = ((const float4*)sxl)[lane];
        for (int h = wid * 32; h < wid * 32 + 32; ++h) {
            const float4 wv = ((const float4*)(w_o + ((size_t)b * HH + h) * II))[lane];
            float p = wv.x * xv.x + wv.y * xv.y + wv.z * xv.z + wv.w * xv.w;
            #pragma unroll
            for (int off = 16; off; off >>= 1) p += __shfl_xor_sync(0xffffffffu, p, off);
            if (lane == 0) s_opre[h] = p + b_o[b * HH + h];
        }
    }
    __syncthreads();

    {   // combine chunk segments in order, then h_fin
        const float* Fp = g_F + (size_t)b * NCHUNK * HH + tid;
        const float* Cp = g_C + (size_t)b * NCHUNK * HH + tid;
        float c = 0.0f;
        #pragma unroll
        for (int ch = 0; ch < NCHUNK; ++ch) c = fmaf(Fp[ch * HH], c, Cp[ch * HH]);
        s_hf[tid] = sigmoidf_(s_opre[tid]) * tanhf(c);
    }
    __syncthreads();

    if (tid < FCN) {
        float a = fc1_b[tid];
        const float* wr = fc1_w + tid * HH;
        #pragma unroll 8
        for (int hh = 0; hh < HH; ++hh) a = fmaf(wr[hh], s_hf[hh], a);
        s_z1[tid] = tanhf(a);
    }
    __syncthreads();

    if (tid == 0) {
        float z0 = fc2_b[0], z1 = fc2_b[1];
        #pragma unroll
        for (int j = 0; j < FCN; ++j) {
            z0 = fmaf(fc2_w[j], s_z1[j], z0);
            z1 = fmaf(fc2_w[FCN + j], s_z1[j], z1);
        }
        const float m = fmaxf(z0, z1);
        const float lse = m + logf(expf(z0 - m) + expf(z1 - m));
        out[b * 2 + 0] = z0 - lse;
        out[b * 2 + 1] = z1 - lse;
    }
}

// ---------------------------------------------------------------------------
extern "C" void kernel_launch(void* const* d_in, const int* in_sizes, int n_in,
                              void* d_out, int out_size) {
    const float* x     = (const float*)d_in[0];
    const float* w_ig  = (const float*)d_in[1];
    const float* w_ii  = (const float*)d_in[2];
    const float* w_if  = (const float*)d_in[3];
    const float* w_io  = (const float*)d_in[4];
    // d_in[5..8] = w_h*: multiplied by zero hidden state in reference -> unused.
    const float* b_g   = (const float*)d_in[9];
    const float* b_i   = (const float*)d_in[10];
    const float* b_f   = (const float*)d_in[11];
    const float* b_o   = (const float*)d_in[12];
    const float* fc1_w = (const float*)d_in[13];
    const float* fc1_b = (const float*)d_in[14];
    const float* fc2_w = (const float*)d_in[15];
    const float* fc2_b = (const float*)d_in[16];
    float* out = (float*)d_out;

    cudaFuncSetAttribute(alstm_main,
                         cudaFuncAttributeMaxDynamicSharedMemorySize, SMEM_BYTES);

    alstm_wconv<<<3 * BB, 256>>>(w_ig, w_ii, w_if);
    alstm_main<<<dim3(NCHUNK, BB), 256, SMEM_BYTES>>>(x, b_g, b_i, b_f);
    alstm_finish<<<BB, 128>>>(x, w_io, b_o, fc1_w, fc1_b, fc2_w, fc2_b, out);
}

// round 11
// speedup vs baseline: 1.5136x; 1.5136x over previous
#include <cuda_runtime.h>
#include <cuda_bf16.h>
#include <math.h>
#include <stdint.h>

#define TT 2048
#define BB 64
#define II 128
#define HH 128
#define FCN 32

#define TC 128                  // timesteps per CTA tile (= GEMM M)
#define NCHUNK (TT / TC)        // 16

// ---------------- global scratch ----------------
// pre-converted W bf16 hi/lo swizzled smem-images: [gate][b][hi 32K | lo 32K]
__device__ __align__(128) unsigned char g_Wimg[3][BB][65536];
// chunk-scan outputs
__device__ float g_F[BB * NCHUNK * HH];
__device__ float g_C[BB * NCHUNK * HH];

// ---------------- smem layout (bytes) ----------------
// MMA phase:  Xhi [0,32K) | Xlo [32K,64K) | W0 [64K,128K) | W1 [128K,192K)
// Act buffers (transposed [h][Tpad], Tpad=133 floats):
//   sP @128K (aliases W1; p written AFTER gate-i MMA)           68096 B
//   sF @0    (aliases X + W0 head; f written AFTER gate-f MMA)  68096 B
#define SX_HI 0
#define SX_LO 32768
#define SW0   65536
#define SW1   131072
#define SP_OFF 131072
#define SF_OFF 0
#define TPAD 133
#define SMEM_BYTES (131072 + 68096)   // 199168

// ---------------- helpers ----------------
__device__ __forceinline__ uint32_t smem_u32(const void* p) {
    uint32_t a;
    asm("{ .reg .u64 t; cvta.to.shared.u64 t, %1; cvt.u32.u64 %0, t; }" : "=r"(a) : "l"(p));
    return a;
}
__device__ __forceinline__ float sigmoid_f(float x) {
    return __fdividef(1.0f, 1.0f + __expf(-x));
}
__device__ __forceinline__ float tanh_f(float x) {
    const float xc = fminf(fmaxf(x, -15.0f), 15.0f);
    const float e = __expf(2.0f * xc);
    return 1.0f - __fdividef(2.0f, e + 1.0f);
}

__device__ __forceinline__ void cp_async16(uint32_t saddr, const void* gaddr) {
    asm volatile("cp.async.cg.shared.global [%0], [%1], 16;" :: "r"(saddr), "l"(gaddr) : "memory");
}
#define CP_COMMIT() asm volatile("cp.async.commit_group;" ::: "memory")
#define CP_WAIT(n)  asm volatile("cp.async.wait_group %0;" :: "n"(n) : "memory")

#define LDSM_X4(r0, r1, r2, r3, addr) \
    asm volatile("ldmatrix.sync.aligned.m8n8.x4.shared.b16 {%0,%1,%2,%3}, [%4];" \
                 : "=r"(r0), "=r"(r1), "=r"(r2), "=r"(r3) : "r"(addr))

#define MMA16816(d, a, b) \
    asm volatile("mma.sync.aligned.m16n8k16.row.col.f32.bf16.bf16.f32 " \
                 "{%0,%1,%2,%3},{%4,%5,%6,%7},{%8,%9},{%0,%1,%2,%3};" \
                 : "+f"((d)[0]), "+f"((d)[1]), "+f"((d)[2]), "+f"((d)[3]) \
                 : "r"((a)[0]), "r"((a)[1]), "r"((a)[2]), "r"((a)[3]), \
                   "r"((b)[0]), "r"((b)[1]))

// convert fp32 rows [64 rows x 128 cols] (row stride rs floats) of a 128x128
// tile -> bf16 hi/lo swizzled images (256B rows; 16B chunk c16 at c16^(r&7)).
// 'half' selects rows [64*half, 64*half+64).
__device__ __forceinline__ void conv_half(const float* __restrict__ src, int rs,
                                          unsigned char* __restrict__ hi,
                                          unsigned char* __restrict__ lo,
                                          int tid, int half) {
    #pragma unroll
    for (int it = 0; it < 4; ++it) {
        const int idx = tid + it * 256 + half * 1024;
        const int r = idx >> 4, c16 = idx & 15;
        const float4* g4 = (const float4*)(src + (size_t)r * rs + c16 * 8);
        const float4 v0 = g4[0], v1 = g4[1];
        const float f[8] = {v0.x, v0.y, v0.z, v0.w, v1.x, v1.y, v1.z, v1.w};
        uint32_t h4[4], l4[4];
        #pragma unroll
        for (int k = 0; k < 4; ++k) {
            __nv_bfloat16 h0 = __float2bfloat16_rn(f[2 * k]);
            __nv_bfloat16 h1 = __float2bfloat16_rn(f[2 * k + 1]);
            __nv_bfloat16 l0 = __float2bfloat16_rn(f[2 * k]     - __bfloat162float(h0));
            __nv_bfloat16 l1 = __float2bfloat16_rn(f[2 * k + 1] - __bfloat162float(h1));
            h4[k] = (uint32_t)__bfloat16_as_ushort(h0) | ((uint32_t)__bfloat16_as_ushort(h1) << 16);
            l4[k] = (uint32_t)__bfloat16_as_ushort(l0) | ((uint32_t)__bfloat16_as_ushort(l1) << 16);
        }
        const uint32_t off = (uint32_t)r * 256u + (uint32_t)(((c16 ^ (r & 7))) * 16);
        *(uint4*)(hi + off) = make_uint4(h4[0], h4[1], h4[2], h4[3]);
        *(uint4*)(lo + off) = make_uint4(l4[0], l4[1], l4[2], l4[3]);
    }
}

// one gate GEMM: acc += Xhi*Whi + Xhi*Wlo + Xlo*Whi   (W image: hi at w, lo at w+32K)
__device__ __forceinline__ void gate_mma(uint32_t xhi, uint32_t xlo, uint32_t w,
                                         float (&acc)[4][4][4], int lane,
                                         int m_base, int n_base) {
    const int arow = (lane & 7) + ((lane >> 3) & 1) * 8;
    const int ak   = (lane >> 4) & 1;
    const int brow = (lane & 7) + ((lane >> 4) & 1) * 8;
    const int bk   = (lane >> 3) & 1;
    #pragma unroll 2
    for (int k = 0; k < 8; ++k) {
        uint32_t a[4][4], bh[2][4], bl[2][4];
        #pragma unroll
        for (int mt = 0; mt < 4; ++mt) {
            const int r = m_base + mt * 16 + arow;
            const uint32_t ad = xhi + (uint32_t)r * 256u
                              + (uint32_t)((((2 * k + ak) ^ (r & 7))) * 16);
            LDSM_X4(a[mt][0], a[mt][1], a[mt][2], a[mt][3], ad);
        }
        #pragma unroll
        for (int nh = 0; nh < 2; ++nh) {
            const int n = n_base + nh * 16 + brow;
            const uint32_t c = (uint32_t)((((2 * k + bk) ^ (n & 7))) * 16)
                             + (uint32_t)n * 256u;
            LDSM_X4(bh[nh][0], bh[nh][1], bh[nh][2], bh[nh][3], w + c);
            LDSM_X4(bl[nh][0], bl[nh][1], bl[nh][2], bl[nh][3], w + 32768u + c);
        }
        #pragma unroll
        for (int mt = 0; mt < 4; ++mt)
            #pragma unroll
            for (int nt = 0; nt < 4; ++nt) {
                MMA16816(acc[mt][nt], a[mt], &bh[nt >> 1][(nt & 1) * 2]);
                MMA16816(acc[mt][nt], a[mt], &bl[nt >> 1][(nt & 1) * 2]);
            }
        #pragma unroll
        for (int mt = 0; mt < 4; ++mt) {
            const int r = m_base + mt * 16 + arow;
            const uint32_t ad = xlo + (uint32_t)r * 256u
                              + (uint32_t)((((2 * k + ak) ^ (r & 7))) * 16);
            LDSM_X4(a[mt][0], a[mt][1], a[mt][2], a[mt][3], ad);
        }
        #pragma unroll
        for (int mt = 0; mt < 4; ++mt)
            #pragma unroll
            for (int nt = 0; nt < 4; ++nt)
                MMA16816(acc[mt][nt], a[mt], &bh[nt >> 1][(nt & 1) * 2]);
    }
}

#define ZERO_ACC(acc) { \
    _Pragma("unroll") for (int mt = 0; mt < 4; ++mt) \
        _Pragma("unroll") for (int nt = 0; nt < 4; ++nt) \
            _Pragma("unroll") for (int e = 0; e < 4; ++e) (acc)[mt][nt][e] = 0.0f; }

// ---------------------------------------------------------------------------
// K0: pre-convert W (g,i,f) per batch into bf16 hi/lo swizzled images
// ---------------------------------------------------------------------------
__global__ __launch_bounds__(256)
void alstm_wconv(const float* __restrict__ wg, const float* __restrict__ wi,
                 const float* __restrict__ wf) {
    const int gate = blockIdx.x >> 7;
    const int b    = (blockIdx.x >> 1) & 63;
    const int half = blockIdx.x & 1;
    const float* src = ((gate == 0) ? wg : (gate == 1) ? wi : wf) + (size_t)b * HH * II;
    conv_half(src, II, g_Wimg[gate][b], g_Wimg[gate][b] + 32768, threadIdx.x, half);
}

// ---------------------------------------------------------------------------
// K1: per (chunk, batch): bf16-split tensor-core gate GEMMs + act + chunk scan
// ---------------------------------------------------------------------------
__global__ __launch_bounds__(256, 1)
void alstm_main(const float* __restrict__ x,
                const float* __restrict__ bg, const float* __restrict__ bi,
                const float* __restrict__ bf) {
    extern __shared__ unsigned char smem[];
    __shared__ float s_pF[HH], s_pC[HH];
    const int chunk = blockIdx.x, b = blockIdx.y;
    const int tid = threadIdx.x, lane = tid & 31, warp = tid >> 5;
    const int m_base = (warp >> 2) * 64;
    const int n_base = (warp & 3) * 32;
    const uint32_t sb = smem_u32(smem);
    float* sPf = (float*)(smem + SP_OFF);
    float* sFf = (float*)(smem + SF_OFF);

    // stage W_g -> W0 (async, overlaps X conversion)
    {
        const unsigned char* src = g_Wimg[0][b];
        #pragma unroll
        for (int i = 0; i < 16; ++i)
            cp_async16(sb + SW0 + tid * 16 + i * 4096, src + tid * 16 + i * 4096);
        CP_COMMIT();
    }
    // convert X chunk [TC x II] -> Xhi/Xlo images
    conv_half(x + ((size_t)(chunk * TC) * BB + b) * II, BB * II,
              smem + SX_HI, smem + SX_LO, tid, 0);
    conv_half(x + ((size_t)(chunk * TC) * BB + b) * II, BB * II,
              smem + SX_HI, smem + SX_LO, tid, 1);
    // stage W_i -> W1
    {
        const unsigned char* src = g_Wimg[1][b];
        #pragma unroll
        for (int i = 0; i < 16; ++i)
            cp_async16(sb + SW1 + tid * 16 + i * 4096, src + tid * 16 + i * 4096);
        CP_COMMIT();
    }
    CP_WAIT(1);          // W_g landed
    __syncthreads();

    float acc[4][4][4], vg[4][4][4];
    const int h_frag = 2 * (lane & 3);
    const int t_frag = lane >> 2;

    // ---- gate g ----
    ZERO_ACC(acc);
    gate_mma(sb + SX_HI, sb + SX_LO, sb + SW0, acc, lane, m_base, n_base);
    #pragma unroll
    for (int nt = 0; nt < 4; ++nt) {
        const int h0 = n_base + nt * 8 + h_frag;
        const float2 bv = *(const float2*)(bg + b * HH + h0);
        #pragma unroll
        for (int mt = 0; mt < 4; ++mt) {
            vg[mt][nt][0] = tanh_f(acc[mt][nt][0] + bv.x);
            vg[mt][nt][1] = tanh_f(acc[mt][nt][1] + bv.y);
            vg[mt][nt][2] = tanh_f(acc[mt][nt][2] + bv.x);
            vg[mt][nt][3] = tanh_f(acc[mt][nt][3] + bv.y);
        }
    }
    __syncthreads();     // everyone done reading W0
    // stage W_f -> W0 (overlaps gate-i MMA)
    {
        const unsigned char* src = g_Wimg[2][b];
        #pragma unroll
        for (int i = 0; i < 16; ++i)
            cp_async16(sb + SW0 + tid * 16 + i * 4096, src + tid * 16 + i * 4096);
        CP_COMMIT();
    }
    CP_WAIT(1);          // W_i landed
    __syncthreads();

    // ---- gate i ----  p = sigmoid(i) * tanh(g), kept in regs
    ZERO_ACC(acc);
    gate_mma(sb + SX_HI, sb + SX_LO, sb + SW1, acc, lane, m_base, n_base);
    #pragma unroll
    for (int nt = 0; nt < 4; ++nt) {
        const int h0 = n_base + nt * 8 + h_frag;
        const float2 bv = *(const float2*)(bi + b * HH + h0);
        #pragma unroll
        for (int mt = 0; mt < 4; ++mt) {
            vg[mt][nt][0] *= sigmoid_f(acc[mt][nt][0] + bv.x);
            vg[mt][nt][1] *= sigmoid_f(acc[mt][nt][1] + bv.y);
            vg[mt][nt][2] *= sigmoid_f(acc[mt][nt][2] + bv.x);
            vg[mt][nt][3] *= sigmoid_f(acc[mt][nt][3] + bv.y);
        }
    }
    __syncthreads();     // ALL warps done reading W1 -> safe to overlay sP
    // store p transposed [h][t] into sP (aliases W1)
    #pragma unroll
    for (int nt = 0; nt < 4; ++nt) {
        const int h0 = n_base + nt * 8 + h_frag;
        #pragma unroll
        for (int mt = 0; mt < 4; ++mt) {
            const int t0 = m_base + mt * 16 + t_frag, t1 = t0 + 8;
            sPf[h0 * TPAD + t0]       = vg[mt][nt][0];
            sPf[(h0 + 1) * TPAD + t0] = vg[mt][nt][1];
            sPf[h0 * TPAD + t1]       = vg[mt][nt][2];
            sPf[(h0 + 1) * TPAD + t1] = vg[mt][nt][3];
        }
    }
    CP_WAIT(0);          // W_f landed
    __syncthreads();

    // ---- gate f ----
    ZERO_ACC(acc);
    gate_mma(sb + SX_HI, sb + SX_LO, sb + SW0, acc, lane, m_base, n_base);
    #pragma unroll
    for (int nt = 0; nt < 4; ++nt) {
        const int h0 = n_base + nt * 8 + h_frag;
        const float2 bv = *(const float2*)(bf + b * HH + h0);
        #pragma unroll
        for (int mt = 0; mt < 4; ++mt) {
            vg[mt][nt][0] = sigmoid_f(acc[mt][nt][0] + bv.x);
            vg[mt][nt][1] = sigmoid_f(acc[mt][nt][1] + bv.y);
            vg[mt][nt][2] = sigmoid_f(acc[mt][nt][2] + bv.x);
            vg[mt][nt][3] = sigmoid_f(acc[mt][nt][3] + bv.y);
        }
    }
    __syncthreads();     // ALL warps done reading X/W0 -> safe to overlay sF
    #pragma unroll
    for (int nt = 0; nt < 4; ++nt) {
        const int h0 = n_base + nt * 8 + h_frag;
        #pragma unroll
        for (int mt = 0; mt < 4; ++mt) {
            const int t0 = m_base + mt * 16 + t_frag, t1 = t0 + 8;
            sFf[h0 * TPAD + t0]       = vg[mt][nt][0];
            sFf[(h0 + 1) * TPAD + t0] = vg[mt][nt][1];
            sFf[h0 * TPAD + t1]       = vg[mt][nt][2];
            sFf[(h0 + 1) * TPAD + t1] = vg[mt][nt][3];
        }
    }
    __syncthreads();

    // ---- chunk-local scan, split in two t-halves across 256 threads ----
    {
        const int h = tid & 127;
        const int half = tid >> 7;
        const float* P  = sPf + h * TPAD + half * 64;
        const float* Fv = sFf + h * TPAD + half * 64;
        float c = 0.0f, F = 1.0f;
        #pragma unroll 8
        for (int t = 0; t < 64; ++t) {
            const float fv = Fv[t];
            c = fmaf(fv, c, P[t]);
            F *= fv;
        }
        if (half) { s_pF[h] = F; s_pC[h] = c; }
        __syncthreads();
        if (!half) {
            const float Fh = s_pF[h], ch = s_pC[h];
            const int idx = (b * NCHUNK + chunk) * HH + h;
            g_C[idx] = fmaf(Fh, c, ch);
            g_F[idx] = F * Fh;
        }
    }
}

// ---------------------------------------------------------------------------
// K2: per batch: o-gate at t=T-1, chunk combine, classifier, log_softmax
// ---------------------------------------------------------------------------
__global__ __launch_bounds__(128)
void alstm_finish(const float* __restrict__ x,
                  const float* __restrict__ w_o,
                  const float* __restrict__ b_o,
                  const float* __restrict__ fc1_w,
                  const float* __restrict__ fc1_b,
                  const float* __restrict__ fc2_w,
                  const float* __restrict__ fc2_b,
                  float* __restrict__ out) {
    const int b = blockIdx.x, tid = threadIdx.x;
    __shared__ __align__(16) float sxl[II];
    __shared__ float s_opre[HH], s_hf[HH], s_z1[FCN];

    sxl[tid] = x[((size_t)(TT - 1) * BB + b) * II + tid];
    __syncthreads();

    {   // o preactivation: warp-cooperative dots
        const int wid = tid >> 5, lane = tid & 31;
        const float4 xv = ((const float4*)sxl)[lane];
        for (int h = wid * 32; h < wid * 32 + 32; ++h) {
            const float4 wv = ((const float4*)(w_o + ((size_t)b * HH + h) * II))[lane];
            float p = wv.x * xv.x + wv.y * xv.y + wv.z * xv.z + wv.w * xv.w;
            #pragma unroll
            for (int off = 16; off; off >>= 1) p += __shfl_xor_sync(0xffffffffu, p, off);
            if (lane == 0) s_opre[h] = p + b_o[b * HH + h];
        }
    }
    __syncthreads();

    {   // combine chunk segments in order, then h_fin (use precise tanh here)
        const float* Fp = g_F + (size_t)b * NCHUNK * HH + tid;
        const float* Cp = g_C + (size_t)b * NCHUNK * HH + tid;
        float c = 0.0f;
        #pragma unroll
        for (int ch = 0; ch < NCHUNK; ++ch) c = fmaf(Fp[ch * HH], c, Cp[ch * HH]);
        s_hf[tid] = (1.0f / (1.0f + expf(-s_opre[tid]))) * tanhf(c);
    }
    __syncthreads();

    if (tid < FCN) {
        float a = fc1_b[tid];
        const float* wr = fc1_w + tid * HH;
        #pragma unroll 8
        for (int hh = 0; hh < HH; ++hh) a = fmaf(wr[hh], s_hf[hh], a);
        s_z1[tid] = tanhf(a);
    }
    __syncthreads();

    if (tid == 0) {
        float z0 = fc2_b[0], z1 = fc2_b[1];
        #pragma unroll
        for (int j = 0; j < FCN; ++j) {
            z0 = fmaf(fc2_w[j], s_z1[j], z0);
            z1 = fmaf(fc2_w[FCN + j], s_z1[j], z1);
        }
        const float m = fmaxf(z0, z1);
        const float lse = m + logf(expf(z0 - m) + expf(z1 - m));
        out[b * 2 + 0] = z0 - lse;
        out[b * 2 + 1] = z1 - lse;
    }
}

// ---------------------------------------------------------------------------
extern "C" void kernel_launch(void* const* d_in, const int* in_sizes, int n_in,
                              void* d_out, int out_size) {
    const float* x     = (const float*)d_in[0];
    const float* w_ig  = (const float*)d_in[1];
    const float* w_ii  = (const float*)d_in[2];
    const float* w_if  = (const float*)d_in[3];
    const float* w_io  = (const float*)d_in[4];
    // d_in[5..8] = w_h*: multiplied by zero hidden state in reference -> unused.
    const float* b_g   = (const float*)d_in[9];
    const float* b_i   = (const float*)d_in[10];
    const float* b_f   = (const float*)d_in[11];
    const float* b_o   = (const float*)d_in[12];
    const float* fc1_w = (const float*)d_in[13];
    const float* fc1_b = (const float*)d_in[14];
    const float* fc2_w = (const float*)d_in[15];
    const float* fc2_b = (const float*)d_in[16];
    float* out = (float*)d_out;

    cudaFuncSetAttribute(alstm_main,
                         cudaFuncAttributeMaxDynamicSharedMemorySize, SMEM_BYTES);

    alstm_wconv<<<3 * BB * 2, 256>>>(w_ig, w_ii, w_if);
    alstm_main<<<dim3(NCHUNK, BB), 256, SMEM_BYTES>>>(x, b_g, b_i, b_f);
    alstm_finish<<<BB, 128>>>(x, w_io, b_o, fc1_w, fc1_b, fc2_w, fc2_b, out);
}